// round 3
// baseline (speedup 1.0000x reference)
#include <cuda_runtime.h>
#include <cstdint>

// Problem constants
#define BB   4
#define HH   56
#define WW   56
#define CC   256
#define NH   8
#define HD   32
#define NN   (HH*WW)          // 3136
#define SS   (NN + 1)         // 3137
#define MROWS (BB * SS)       // 12548

// Scratch (device globals; no allocations allowed)
__device__ float g_q[(size_t)BB * NH * SS * HD];
__device__ float g_k[(size_t)BB * NH * SS * HD];
__device__ float g_v[(size_t)BB * NH * SS * HD];
__device__ float g_attn[(size_t)BB * SS * CC];

// ---------------------------------------------------------------------------
// Unified tiled GEMM: C[M,N] = A[M,256] * W[N,256]^T (+bias)
// mode 0: A = concat(cls, x) gathered; scatter outputs into g_q/g_k/g_v
// mode 1: A = g_attn; outputs -> d_out (x part / cls part) with bias
// Tile 128x128, 256 threads, 8x8 microtile with 16-strided rows/cols.
// ---------------------------------------------------------------------------
__global__ __launch_bounds__(256) void gemm_kernel(
    const float* __restrict__ x, const float* __restrict__ cls,
    const float* __restrict__ w, const float* __restrict__ bias,
    float* __restrict__ out_x, float* __restrict__ out_cls, int mode)
{
    __shared__ float As[16][132];
    __shared__ float Bs[16][132];

    const int t    = threadIdx.x;
    const int row0 = blockIdx.x * 128;
    const int col0 = blockIdx.y * 128;
    const int ty   = t >> 4;
    const int tx   = t & 15;

    float acc[8][8];
#pragma unroll
    for (int i = 0; i < 8; i++)
#pragma unroll
        for (int j = 0; j < 8; j++) acc[i][j] = 0.f;

    for (int k0 = 0; k0 < 256; k0 += 16) {
#pragma unroll
        for (int lp = 0; lp < 2; lp++) {
            int f  = t + lp * 256;      // float4 index 0..511
            int ar = f >> 2;            // 0..127
            int ak = (f & 3) << 2;      // 0,4,8,12
            // A tile
            int row = row0 + ar;
            float4 av = make_float4(0.f, 0.f, 0.f, 0.f);
            if (row < MROWS) {
                const float* src;
                if (mode == 0) {
                    int b = row / SS;
                    int s = row - b * SS;
                    src = (s == 0) ? (cls + (size_t)b * CC)
                                   : (x + ((size_t)b * NN + (s - 1)) * CC);
                } else {
                    src = g_attn + (size_t)row * CC;
                }
                av = *(const float4*)(src + k0 + ak);
            }
            As[ak + 0][ar] = av.x; As[ak + 1][ar] = av.y;
            As[ak + 2][ar] = av.z; As[ak + 3][ar] = av.w;
            // B tile (W rows are output columns)
            int col = col0 + ar;
            float4 bv = *(const float4*)(w + (size_t)col * CC + k0 + ak);
            Bs[ak + 0][ar] = bv.x; Bs[ak + 1][ar] = bv.y;
            Bs[ak + 2][ar] = bv.z; Bs[ak + 3][ar] = bv.w;
        }
        __syncthreads();

#pragma unroll
        for (int kk = 0; kk < 16; kk++) {
            float a[8], b[8];
#pragma unroll
            for (int i = 0; i < 8; i++) a[i] = As[kk][ty + 16 * i];
#pragma unroll
            for (int j = 0; j < 8; j++) b[j] = Bs[kk][tx + 16 * j];
#pragma unroll
            for (int i = 0; i < 8; i++)
#pragma unroll
                for (int j = 0; j < 8; j++) acc[i][j] += a[i] * b[j];
        }
        __syncthreads();
    }

#pragma unroll
    for (int i = 0; i < 8; i++) {
        int row = row0 + ty + 16 * i;
        if (row >= MROWS) continue;
        int b = row / SS;
        int s = row - b * SS;
#pragma unroll
        for (int j = 0; j < 8; j++) {
            int n = col0 + tx + 16 * j;
            float v = acc[i][j];
            if (mode == 0) {
                int c3  = n >> 8;
                int rem = n & 255;
                int h   = rem >> 5;
                int d   = rem & 31;
                float* dst = (c3 == 0) ? g_q : ((c3 == 1) ? g_k : g_v);
                dst[(((size_t)b * NH + h) * SS + s) * HD + d] = v;
            } else {
                v += bias[n];
                if (s == 0) out_cls[(size_t)b * CC + n] = v;
                else        out_x[((size_t)b * NN + (s - 1)) * CC + n] = v;
            }
        }
    }
}

// ---------------------------------------------------------------------------
// Flash-style attention (no running max: logits have sigma ~0.1, exp is safe).
// Block = 128 threads, 64 queries x full key stream in 32-key tiles.
// Thread microtile: 4 rows (stride 16) x 4 dims (stride 8) — all LDS patterns
// are bank-conflict-free with intra-warp broadcast.
// ---------------------------------------------------------------------------
__global__ __launch_bounds__(128) void attn_kernel()
{
    __shared__ float qs[64][33];
    __shared__ float ks[32][33];
    __shared__ float vs[32][32];
    __shared__ float ps[64][33];

    const int t  = threadIdx.x;
    const int bh = blockIdx.y;              // b*8 + h
    const int q0 = blockIdx.x * 64;
    const float* qb = g_q + (size_t)bh * SS * HD;
    const float* kb = g_k + (size_t)bh * SS * HD;
    const float* vb = g_v + (size_t)bh * SS * HD;

    // load Q tile (64x32)
#pragma unroll
    for (int lp = 0; lp < 4; lp++) {
        int f = t + lp * 128;              // float4 idx 0..511
        int r = f >> 3;                    // 0..63
        int o = (f & 7) << 2;              // 0..28
        float4 v4 = make_float4(0.f, 0.f, 0.f, 0.f);
        if (q0 + r < SS) v4 = *(const float4*)(qb + (size_t)(q0 + r) * HD + o);
        qs[r][o] = v4.x; qs[r][o+1] = v4.y; qs[r][o+2] = v4.z; qs[r][o+3] = v4.w;
    }

    const int rg = t & 15;                 // row group 0..15
    const int cg = t >> 4;                 // col group 0..7
    const float scale = 0.17677669529663687f;   // 1/sqrt(32)

    float acc[4][4];
    float l[4];
#pragma unroll
    for (int i = 0; i < 4; i++) {
        l[i] = 0.f;
#pragma unroll
        for (int j = 0; j < 4; j++) acc[i][j] = 0.f;
    }

    const int KT = (SS + 31) / 32;         // 99
    for (int kt = 0; kt < KT; kt++) {
        __syncthreads();
        // load K,V tiles (32x32 each)
#pragma unroll
        for (int lp = 0; lp < 2; lp++) {
            int f = t + lp * 128;          // 0..255
            int r = f >> 3;
            int o = (f & 7) << 2;
            int grow = kt * 32 + r;
            float4 kv = make_float4(0.f, 0.f, 0.f, 0.f);
            float4 vv = kv;
            if (grow < SS) {
                kv = *(const float4*)(kb + (size_t)grow * HD + o);
                vv = *(const float4*)(vb + (size_t)grow * HD + o);
            }
            ks[r][o] = kv.x; ks[r][o+1] = kv.y; ks[r][o+2] = kv.z; ks[r][o+3] = kv.w;
            *(float4*)&vs[r][o] = vv;
        }
        __syncthreads();

        // QK scores + exp -> ps
        float sc[4][4];
#pragma unroll
        for (int i = 0; i < 4; i++)
#pragma unroll
            for (int j = 0; j < 4; j++) sc[i][j] = 0.f;
#pragma unroll
        for (int kk = 0; kk < 32; kk++) {
            float qv[4], kv[4];
#pragma unroll
            for (int i = 0; i < 4; i++) qv[i] = qs[rg + 16 * i][kk];
#pragma unroll
            for (int j = 0; j < 4; j++) kv[j] = ks[cg + 8 * j][kk];
#pragma unroll
            for (int i = 0; i < 4; i++)
#pragma unroll
                for (int j = 0; j < 4; j++) sc[i][j] += qv[i] * kv[j];
        }
#pragma unroll
        for (int j = 0; j < 4; j++) {
            int jg = kt * 32 + cg + 8 * j;
            bool valid = (jg < SS);
#pragma unroll
            for (int i = 0; i < 4; i++) {
                float p = valid ? __expf(sc[i][j] * scale) : 0.f;
                ps[rg + 16 * i][cg + 8 * j] = p;
            }
        }
        __syncthreads();

        // PV + running denominator
#pragma unroll 8
        for (int jk = 0; jk < 32; jk++) {
            float pv[4], vv[4];
#pragma unroll
            for (int i = 0; i < 4; i++) pv[i] = ps[rg + 16 * i][jk];
#pragma unroll
            for (int j = 0; j < 4; j++) vv[j] = vs[jk][cg + 8 * j];
#pragma unroll
            for (int i = 0; i < 4; i++) {
                l[i] += pv[i];
#pragma unroll
                for (int j = 0; j < 4; j++) acc[i][j] += pv[i] * vv[j];
            }
        }
    }

    // write out: g_attn[b][s][h*32 + d]
    const int b = bh >> 3;
    const int h = bh & 7;
#pragma unroll
    for (int i = 0; i < 4; i++) {
        int sr = q0 + rg + 16 * i;
        if (sr >= SS) continue;
        float inv = 1.f / l[i];
#pragma unroll
        for (int j = 0; j < 4; j++) {
            g_attn[((size_t)b * SS + sr) * CC + h * HD + cg + 8 * j] = acc[i][j] * inv;
        }
    }
}

// ---------------------------------------------------------------------------
// LePE: 5x5 depthwise conv (SAME) over x (NHWC), added in place into g_attn
// rows 1..N (plus lepe bias). One block per (b,y,x), 256 threads over channels.
// ---------------------------------------------------------------------------
__global__ __launch_bounds__(256) void lepe_kernel(
    const float* __restrict__ x, const float* __restrict__ lw,
    const float* __restrict__ lb)
{
    __shared__ float wsh[CC][25];
    const int c  = threadIdx.x;
    const int xw = blockIdx.x;
    const int yh = blockIdx.y;
    const int b  = blockIdx.z;

    // cooperative coalesced weight load: 256*25 floats
    for (int i = c; i < CC * 25; i += 256) {
        wsh[i / 25][i % 25] = lw[i];
    }
    __syncthreads();

    float sum = lb[c];
#pragma unroll
    for (int ky = 0; ky < 5; ky++) {
        int yy = yh + ky - 2;
        if (yy < 0 || yy >= HH) continue;
#pragma unroll
        for (int kx = 0; kx < 5; kx++) {
            int xx = xw + kx - 2;
            if (xx < 0 || xx >= WW) continue;
            sum += x[(((size_t)b * HH + yy) * WW + xx) * CC + c] * wsh[c][ky * 5 + kx];
        }
    }
    g_attn[((size_t)b * SS + 1 + yh * WW + xw) * CC + c] += sum;
}

// ---------------------------------------------------------------------------
extern "C" void kernel_launch(void* const* d_in, const int* in_sizes, int n_in,
                              void* d_out, int out_size)
{
    const float* x      = (const float*)d_in[0];   // (4,56,56,256)
    const float* cls    = (const float*)d_in[1];   // (4,1,256)
    const float* qkv_w  = (const float*)d_in[2];   // (768,256)
    const float* proj_w = (const float*)d_in[3];   // (256,256)
    const float* proj_b = (const float*)d_in[4];   // (256)
    const float* lepe_w = (const float*)d_in[5];   // (256,1,5,5)
    const float* lepe_b = (const float*)d_in[6];   // (256)

    float* out_x   = (float*)d_out;
    float* out_cls = (float*)d_out + in_sizes[0];  // x_out elems first, then cls_out

    // 1) QKV projection: (12548 x 768) = Xcat @ W^T, scattered to g_q/g_k/g_v
    gemm_kernel<<<dim3((MROWS + 127) / 128, 768 / 128), 256>>>(
        x, cls, qkv_w, nullptr, nullptr, nullptr, 0);

    // 2) Attention (flash-style, fp32)
    attn_kernel<<<dim3((SS + 63) / 64, BB * NH), 128>>>();

    // 3) LePE depthwise conv added in place to g_attn rows 1..N
    lepe_kernel<<<dim3(WW, HH, BB), 256>>>(x, lepe_w, lepe_b);

    // 4) Output projection + bias, split to x_out / cls_out
    gemm_kernel<<<dim3((MROWS + 127) / 128, CC / 128), 256>>>(
        nullptr, nullptr, proj_w, proj_b, out_x, out_cls, 1);
}

// round 5
// speedup vs baseline: 2.2349x; 2.2349x over previous
#include <cuda_runtime.h>
#include <cuda_bf16.h>
#include <cstdint>

// Problem constants
#define BB   4
#define HH   56
#define WW   56
#define CC   256
#define NH   8
#define HD   32
#define NN   (HH*WW)          // 3136
#define SS   (NN + 1)         // 3137
#define SP   3200             // padded seq stride (50 * 64)
#define MROWS (BB * SS)       // 12548
#define BHN  (BB * NH)        // 32

// Scratch (device globals; zero-initialized — padding rows stay 0)
__device__ float g_attn[(size_t)BB * SS * CC];
__device__ __nv_bfloat16 g_qh[(size_t)BHN * SP * HD];   // Q pre-scaled by 1/sqrt(hd)*log2(e)
__device__ __nv_bfloat16 g_ql[(size_t)BHN * SP * HD];
__device__ __nv_bfloat16 g_kh[(size_t)BHN * SP * HD];
__device__ __nv_bfloat16 g_kl[(size_t)BHN * SP * HD];
__device__ __nv_bfloat16 g_vth[(size_t)BHN * HD * SP];  // V^T: [bh][d][s]
__device__ __nv_bfloat16 g_vtl[(size_t)BHN * HD * SP];

// ---------------------------------------------------------------------------
// mma.sync m16n8k16 bf16 (baseline PTX, works at sm_103) — HMMA on tensor pipe
// ---------------------------------------------------------------------------
__device__ __forceinline__ void mma16816(float* d, const uint32_t* a,
                                         const uint32_t* b, const float* c) {
    asm volatile(
        "mma.sync.aligned.m16n8k16.row.col.f32.bf16.bf16.f32 "
        "{%0,%1,%2,%3}, {%4,%5,%6,%7}, {%8,%9}, {%10,%11,%12,%13};"
        : "=f"(d[0]), "=f"(d[1]), "=f"(d[2]), "=f"(d[3])
        : "r"(a[0]), "r"(a[1]), "r"(a[2]), "r"(a[3]),
          "r"(b[0]), "r"(b[1]),
          "f"(c[0]), "f"(c[1]), "f"(c[2]), "f"(c[3]));
}

// pack two f32 -> bf16x2 (lo half = first arg)
__device__ __forceinline__ uint32_t packbf(float lo, float hi) {
    uint32_t r;
    asm("cvt.rn.bf16x2.f32 %0, %1, %2;" : "=r"(r) : "f"(hi), "f"(lo));
    return r;
}

// ---------------------------------------------------------------------------
// Unified tiled GEMM: C[M,N] = A[M,256] * W[N,256]^T (+bias)
// mode 0: A = concat(cls, x); outputs -> bf16 hi/lo splits of Q/K + V^T
//         (Q pre-scaled by 1/sqrt(32)*log2(e) so attention uses raw exp2)
// mode 1: A = g_attn; outputs -> d_out (x part / cls part) with bias
// ---------------------------------------------------------------------------
__global__ __launch_bounds__(256) void gemm_kernel(
    const float* __restrict__ x, const float* __restrict__ cls,
    const float* __restrict__ w, const float* __restrict__ bias,
    float* __restrict__ out_x, float* __restrict__ out_cls, int mode)
{
    __shared__ float As[16][132];
    __shared__ float Bs[16][132];

    const int t    = threadIdx.x;
    const int row0 = blockIdx.x * 128;
    const int col0 = blockIdx.y * 128;
    const int ty   = t >> 4;
    const int tx   = t & 15;

    float acc[8][8];
#pragma unroll
    for (int i = 0; i < 8; i++)
#pragma unroll
        for (int j = 0; j < 8; j++) acc[i][j] = 0.f;

    for (int k0 = 0; k0 < 256; k0 += 16) {
#pragma unroll
        for (int lp = 0; lp < 2; lp++) {
            int f  = t + lp * 256;
            int ar = f >> 2;
            int ak = (f & 3) << 2;
            int row = row0 + ar;
            float4 av = make_float4(0.f, 0.f, 0.f, 0.f);
            if (row < MROWS) {
                const float* src;
                if (mode == 0) {
                    int b = row / SS;
                    int s = row - b * SS;
                    src = (s == 0) ? (cls + (size_t)b * CC)
                                   : (x + ((size_t)b * NN + (s - 1)) * CC);
                } else {
                    src = g_attn + (size_t)row * CC;
                }
                av = *(const float4*)(src + k0 + ak);
            }
            As[ak + 0][ar] = av.x; As[ak + 1][ar] = av.y;
            As[ak + 2][ar] = av.z; As[ak + 3][ar] = av.w;
            int col = col0 + ar;
            float4 bv = *(const float4*)(w + (size_t)col * CC + k0 + ak);
            Bs[ak + 0][ar] = bv.x; Bs[ak + 1][ar] = bv.y;
            Bs[ak + 2][ar] = bv.z; Bs[ak + 3][ar] = bv.w;
        }
        __syncthreads();

#pragma unroll
        for (int kk = 0; kk < 16; kk++) {
            float a[8], b[8];
#pragma unroll
            for (int i = 0; i < 8; i++) a[i] = As[kk][ty + 16 * i];
#pragma unroll
            for (int j = 0; j < 8; j++) b[j] = Bs[kk][tx + 16 * j];
#pragma unroll
            for (int i = 0; i < 8; i++)
#pragma unroll
                for (int j = 0; j < 8; j++) acc[i][j] += a[i] * b[j];
        }
        __syncthreads();
    }

    const float QSCALE = 0.17677669529663687f * 1.4426950408889634f;

#pragma unroll
    for (int i = 0; i < 8; i++) {
        int row = row0 + ty + 16 * i;
        if (row >= MROWS) continue;
        int b = row / SS;
        int s = row - b * SS;
#pragma unroll
        for (int j = 0; j < 8; j++) {
            int n = col0 + tx + 16 * j;
            float v = acc[i][j];
            if (mode == 0) {
                int c3  = n >> 8;
                int rem = n & 255;
                int h   = rem >> 5;
                int d   = rem & 31;
                int bh  = b * NH + h;
                if (c3 == 0) v *= QSCALE;
                __nv_bfloat16 hi = __float2bfloat16(v);
                __nv_bfloat16 lo = __float2bfloat16(v - __bfloat162float(hi));
                if (c3 == 2) {
                    size_t idx = ((size_t)bh * HD + d) * SP + s;
                    g_vth[idx] = hi; g_vtl[idx] = lo;
                } else {
                    size_t idx = ((size_t)bh * SP + s) * HD + d;
                    if (c3 == 0) { g_qh[idx] = hi; g_ql[idx] = lo; }
                    else         { g_kh[idx] = hi; g_kl[idx] = lo; }
                }
            } else {
                v += bias[n];
                if (s == 0) out_cls[(size_t)b * CC + n] = v;
                else        out_x[((size_t)b * NN + (s - 1)) * CC + n] = v;
            }
        }
    }
}

// ---------------------------------------------------------------------------
// Flash attention on mma.sync bf16 with hi/lo residual splitting.
// Block: 256 threads (8 warps), 128 q rows (16 per warp). Key tiles of 64.
// S = qh*kh + ql*kh + qh*kl ; P = exp2(S) (scale folded into Q) ;
// O += ph*vh + pl*vh + ph*vl ; P never touches smem (C-frag == A-frag layout).
// ---------------------------------------------------------------------------
#define TKEY 64
#define QTILE 128
#define STK 40     // K smem row stride in halves (conflict-free: banks 20g+m)
#define STV 72     // V^T smem row stride in halves (banks 4d+m)
#define KT_TILES (SP / TKEY)   // 50

__global__ __launch_bounds__(256, 2) void attn_mma_kernel()
{
    __shared__ alignas(16) uint16_t Kh[64 * STK];
    __shared__ alignas(16) uint16_t Kl[64 * STK];
    __shared__ alignas(16) uint16_t Vh[32 * STV];
    __shared__ alignas(16) uint16_t Vl[32 * STV];

    const int t    = threadIdx.x;
    const int w    = t >> 5;
    const int lane = t & 31;
    const int g    = lane >> 2;         // row-in-frag 0..7
    const int m2   = (lane & 3) * 2;    // k-pair offset
    const int bh   = blockIdx.y;
    const int q0   = blockIdx.x * QTILE;
    const int qrow = q0 + w * 16;

    // Load Q fragments once (hi/lo, 2 k-chunks) straight from gmem
    uint32_t qa_h[2][4], qa_l[2][4];
    {
        const __nv_bfloat16* qh = g_qh + (size_t)bh * SP * HD;
        const __nv_bfloat16* ql = g_ql + (size_t)bh * SP * HD;
        int r0 = qrow + g, r1 = qrow + g + 8;
        bool v0 = r0 < SS, v1 = r1 < SS;
#pragma unroll
        for (int kc = 0; kc < 2; kc++) {
            int d0 = kc * 16 + m2, d1 = d0 + 8;
            qa_h[kc][0] = v0 ? *(const uint32_t*)(qh + (size_t)r0 * HD + d0) : 0u;
            qa_h[kc][1] = v1 ? *(const uint32_t*)(qh + (size_t)r1 * HD + d0) : 0u;
            qa_h[kc][2] = v0 ? *(const uint32_t*)(qh + (size_t)r0 * HD + d1) : 0u;
            qa_h[kc][3] = v1 ? *(const uint32_t*)(qh + (size_t)r1 * HD + d1) : 0u;
            qa_l[kc][0] = v0 ? *(const uint32_t*)(ql + (size_t)r0 * HD + d0) : 0u;
            qa_l[kc][1] = v1 ? *(const uint32_t*)(ql + (size_t)r1 * HD + d0) : 0u;
            qa_l[kc][2] = v0 ? *(const uint32_t*)(ql + (size_t)r0 * HD + d1) : 0u;
            qa_l[kc][3] = v1 ? *(const uint32_t*)(ql + (size_t)r1 * HD + d1) : 0u;
        }
    }

    float o[4][4];
#pragma unroll
    for (int i = 0; i < 4; i++)
#pragma unroll
        for (int j = 0; j < 4; j++) o[i][j] = 0.f;
    float la = 0.f, lb = 0.f;

    // load indices (per thread) for K/V tiles
    const int kr = t >> 2, kc4 = t & 3;      // K: 64 rows x 4 uint4
    const int vr = t >> 3, vc8 = t & 7;      // V: 32 rows x 8 uint4

    for (int kt = 0; kt < KT_TILES; kt++) {
        __syncthreads();
        {
            size_t ksrc = ((size_t)bh * SP + (size_t)kt * TKEY + kr) * HD + kc4 * 8;
            *(uint4*)(Kh + kr * STK + kc4 * 8) = *(const uint4*)(g_kh + ksrc);
            *(uint4*)(Kl + kr * STK + kc4 * 8) = *(const uint4*)(g_kl + ksrc);
            size_t vsrc = ((size_t)bh * HD + vr) * SP + (size_t)kt * TKEY + vc8 * 8;
            *(uint4*)(Vh + vr * STV + vc8 * 8) = *(const uint4*)(g_vth + vsrc);
            *(uint4*)(Vl + vr * STV + vc8 * 8) = *(const uint4*)(g_vtl + vsrc);
        }
        __syncthreads();

        // ---- S = Q K^T (3 residual terms), 8 n-chunks of 8 keys ----
        float sf[8][4];
#pragma unroll
        for (int jn = 0; jn < 8; jn++) {
#pragma unroll
            for (int c = 0; c < 4; c++) sf[jn][c] = 0.f;
            const uint16_t* kbase = Kh + (jn * 8 + g) * STK;
            const uint16_t* kbasl = Kl + (jn * 8 + g) * STK;
#pragma unroll
            for (int kc = 0; kc < 2; kc++) {
                uint32_t bhf[2], blf[2];
                bhf[0] = *(const uint32_t*)(kbase + kc * 16 + m2);
                bhf[1] = *(const uint32_t*)(kbase + kc * 16 + m2 + 8);
                blf[0] = *(const uint32_t*)(kbasl + kc * 16 + m2);
                blf[1] = *(const uint32_t*)(kbasl + kc * 16 + m2 + 8);
                mma16816(sf[jn], qa_h[kc], bhf, sf[jn]);
                mma16816(sf[jn], qa_l[kc], bhf, sf[jn]);
                mma16816(sf[jn], qa_h[kc], blf, sf[jn]);
            }
        }

        // ---- softmax numerator: p = exp2(s); split to bf16 hi/lo in-reg ----
        uint32_t ph[8][2], pl[8][2];
        const int kb = kt * TKEY;
#pragma unroll
        for (int jn = 0; jn < 8; jn++) {
            int col0 = kb + jn * 8 + m2;
            bool c0v = col0 < SS, c1v = (col0 + 1) < SS;
            float p0 = c0v ? exp2f(sf[jn][0]) : 0.f;
            float p1 = c1v ? exp2f(sf[jn][1]) : 0.f;
            float p2 = c0v ? exp2f(sf[jn][2]) : 0.f;
            float p3 = c1v ? exp2f(sf[jn][3]) : 0.f;
            la += p0 + p1;
            lb += p2 + p3;
            uint32_t h0 = packbf(p0, p1);
            uint32_t h1 = packbf(p2, p3);
            float r0 = p0 - __uint_as_float(h0 << 16);
            float r1 = p1 - __uint_as_float(h0 & 0xffff0000u);
            float r2 = p2 - __uint_as_float(h1 << 16);
            float r3 = p3 - __uint_as_float(h1 & 0xffff0000u);
            ph[jn][0] = h0; ph[jn][1] = h1;
            pl[jn][0] = packbf(r0, r1);
            pl[jn][1] = packbf(r2, r3);
        }

        // ---- O += P V (3 residual terms), 4 k-chunks x 4 dim-chunks ----
#pragma unroll
        for (int kc2 = 0; kc2 < 4; kc2++) {
            uint32_t pa_h[4] = { ph[2*kc2][0], ph[2*kc2][1],
                                 ph[2*kc2+1][0], ph[2*kc2+1][1] };
            uint32_t pa_l[4] = { pl[2*kc2][0], pl[2*kc2][1],
                                 pl[2*kc2+1][0], pl[2*kc2+1][1] };
#pragma unroll
            for (int jn2 = 0; jn2 < 4; jn2++) {
                const uint16_t* vbh = Vh + (jn2 * 8 + g) * STV + kc2 * 16 + m2;
                const uint16_t* vbl = Vl + (jn2 * 8 + g) * STV + kc2 * 16 + m2;
                uint32_t bvh[2] = { *(const uint32_t*)vbh,
                                    *(const uint32_t*)(vbh + 8) };
                uint32_t bvl[2] = { *(const uint32_t*)vbl,
                                    *(const uint32_t*)(vbl + 8) };
                mma16816(o[jn2], pa_h, bvh, o[jn2]);
                mma16816(o[jn2], pa_l, bvh, o[jn2]);
                mma16816(o[jn2], pa_h, bvl, o[jn2]);
            }
        }
    }

    // ---- normalize + store ----
    la += __shfl_xor_sync(0xffffffffu, la, 1);
    la += __shfl_xor_sync(0xffffffffu, la, 2);
    lb += __shfl_xor_sync(0xffffffffu, lb, 1);
    lb += __shfl_xor_sync(0xffffffffu, lb, 2);
    const float ia = 1.f / la, ib = 1.f / lb;

    const int b = bh >> 3;
    const int h = bh & 7;
    const int r0 = qrow + g, r1 = qrow + g + 8;
    if (r0 < SS) {
        float* dst = g_attn + ((size_t)b * SS + r0) * CC + h * HD + m2;
#pragma unroll
        for (int jn2 = 0; jn2 < 4; jn2++)
            *(float2*)(dst + jn2 * 8) = make_float2(o[jn2][0] * ia, o[jn2][1] * ia);
    }
    if (r1 < SS) {
        float* dst = g_attn + ((size_t)b * SS + r1) * CC + h * HD + m2;
#pragma unroll
        for (int jn2 = 0; jn2 < 4; jn2++)
            *(float2*)(dst + jn2 * 8) = make_float2(o[jn2][2] * ib, o[jn2][3] * ib);
    }
}

// ---------------------------------------------------------------------------
// LePE: 5x5 depthwise conv (SAME) over x (NHWC), added in place into g_attn
// ---------------------------------------------------------------------------
__global__ __launch_bounds__(256) void lepe_kernel(
    const float* __restrict__ x, const float* __restrict__ lw,
    const float* __restrict__ lb)
{
    __shared__ float wsh[CC][25];
    const int c  = threadIdx.x;
    const int xw = blockIdx.x;
    const int yh = blockIdx.y;
    const int b  = blockIdx.z;

    for (int i = c; i < CC * 25; i += 256) {
        wsh[i / 25][i % 25] = lw[i];
    }
    __syncthreads();

    float sum = lb[c];
#pragma unroll
    for (int ky = 0; ky < 5; ky++) {
        int yy = yh + ky - 2;
        if (yy < 0 || yy >= HH) continue;
#pragma unroll
        for (int kx = 0; kx < 5; kx++) {
            int xx = xw + kx - 2;
            if (xx < 0 || xx >= WW) continue;
            sum += x[(((size_t)b * HH + yy) * WW + xx) * CC + c] * wsh[c][ky * 5 + kx];
        }
    }
    g_attn[((size_t)b * SS + 1 + yh * WW + xw) * CC + c] += sum;
}

// ---------------------------------------------------------------------------
extern "C" void kernel_launch(void* const* d_in, const int* in_sizes, int n_in,
                              void* d_out, int out_size)
{
    const float* x      = (const float*)d_in[0];
    const float* cls    = (const float*)d_in[1];
    const float* qkv_w  = (const float*)d_in[2];
    const float* proj_w = (const float*)d_in[3];
    const float* proj_b = (const float*)d_in[4];
    const float* lepe_w = (const float*)d_in[5];
    const float* lepe_b = (const float*)d_in[6];

    float* out_x   = (float*)d_out;
    float* out_cls = (float*)d_out + in_sizes[0];

    // 1) QKV projection -> bf16 hi/lo Q (pre-scaled), K, transposed V
    gemm_kernel<<<dim3((MROWS + 127) / 128, 768 / 128), 256>>>(
        x, cls, qkv_w, nullptr, nullptr, nullptr, 0);

    // 2) mma.sync flash attention
    attn_mma_kernel<<<dim3((SS + QTILE - 1) / QTILE, BHN), 256>>>();

    // 3) LePE depthwise conv added into g_attn
    lepe_kernel<<<dim3(WW, HH, BB), 256>>>(x, lepe_w, lepe_b);

    // 4) Output projection
    gemm_kernel<<<dim3((MROWS + 127) / 128, CC / 128), 256>>>(
        nullptr, nullptr, proj_w, proj_b, out_x, out_cls, 1);
}

// round 6
// speedup vs baseline: 3.4135x; 1.5274x over previous
#include <cuda_runtime.h>
#include <cuda_fp16.h>
#include <cstdint>

// Problem constants
#define BB   4
#define HH   56
#define WW   56
#define CC   256
#define NH   8
#define HD   32
#define NN   (HH*WW)          // 3136
#define SS   (NN + 1)         // 3137
#define SP   3200             // padded seq stride (25*128 exactly)
#define MROWS (BB * SS)       // 12548
#define BHN  (BB * NH)        // 32

// Scratch (device globals; zero-initialized — padding stays 0)
__device__ float g_attn[(size_t)BB * SS * CC];
__device__ __half g_q[(size_t)BHN * SP * HD];    // pre-scaled by 1/sqrt(hd)*log2(e)
__device__ __half g_k[(size_t)BHN * SP * HD];
__device__ __half g_vt[(size_t)BHN * HD * SP];   // V^T: [bh][d][s]
__device__ float  g_vsum[BHN * HD];              // fp32 exact sum_s V[s][d]

// ---------------------------------------------------------------------------
// PTX helpers (baseline-PTX instructions only: sm_80/75 features, OK at sm_103)
// ---------------------------------------------------------------------------
__device__ __forceinline__ uint32_t smem_u32(const void* p) {
    uint32_t a;
    asm("{ .reg .u64 t; cvta.to.shared.u64 t, %1; cvt.u32.u64 %0, t; }"
        : "=r"(a) : "l"(p));
    return a;
}
__device__ __forceinline__ void mma16816h(float* d, const uint32_t* a,
                                          const uint32_t* b, const float* c) {
    asm volatile(
        "mma.sync.aligned.m16n8k16.row.col.f32.f16.f16.f32 "
        "{%0,%1,%2,%3}, {%4,%5,%6,%7}, {%8,%9}, {%10,%11,%12,%13};"
        : "=f"(d[0]), "=f"(d[1]), "=f"(d[2]), "=f"(d[3])
        : "r"(a[0]), "r"(a[1]), "r"(a[2]), "r"(a[3]),
          "r"(b[0]), "r"(b[1]),
          "f"(c[0]), "f"(c[1]), "f"(c[2]), "f"(c[3]));
}
__device__ __forceinline__ void ldm4(uint32_t* r, uint32_t a) {
    asm volatile("ldmatrix.sync.aligned.m8n8.x4.shared.b16 {%0,%1,%2,%3}, [%4];"
                 : "=r"(r[0]), "=r"(r[1]), "=r"(r[2]), "=r"(r[3]) : "r"(a));
}
__device__ __forceinline__ float ex2(float x) {
    float r;
    asm("ex2.approx.ftz.f32 %0, %1;" : "=f"(r) : "f"(x));
    return r;
}
// pack two f32 -> f16x2 (lo half = first arg)
__device__ __forceinline__ uint32_t packh(float lo, float hi) {
    uint32_t r;
    asm("cvt.rn.f16x2.f32 %0, %1, %2;" : "=r"(r) : "f"(hi), "f"(lo));
    return r;
}
#define CP16(dst, src) asm volatile("cp.async.cg.shared.global [%0], [%1], 16;" :: "r"(dst), "l"(src) : "memory")
#define CPCOMMIT()     asm volatile("cp.async.commit_group;" ::: "memory")
#define CPWAIT1()      asm volatile("cp.async.wait_group 1;" ::: "memory")

// ---------------------------------------------------------------------------
// Unified tiled GEMM: C[M,N] = A[M,256] * W[N,256]^T (+bias)
// mode 0: A = concat(cls, x); outputs fp16 Q (pre-scaled), K, V^T
// mode 1: A = g_attn; outputs -> d_out (x part / cls part) with bias
// ---------------------------------------------------------------------------
__global__ __launch_bounds__(256) void gemm_kernel(
    const float* __restrict__ x, const float* __restrict__ cls,
    const float* __restrict__ w, const float* __restrict__ bias,
    float* __restrict__ out_x, float* __restrict__ out_cls, int mode)
{
    __shared__ float As[16][132];
    __shared__ float Bs[16][132];

    const int t    = threadIdx.x;
    const int row0 = blockIdx.x * 128;
    const int col0 = blockIdx.y * 128;
    const int ty   = t >> 4;
    const int tx   = t & 15;

    float acc[8][8];
#pragma unroll
    for (int i = 0; i < 8; i++)
#pragma unroll
        for (int j = 0; j < 8; j++) acc[i][j] = 0.f;

    for (int k0 = 0; k0 < 256; k0 += 16) {
#pragma unroll
        for (int lp = 0; lp < 2; lp++) {
            int f  = t + lp * 256;
            int ar = f >> 2;
            int ak = (f & 3) << 2;
            int row = row0 + ar;
            float4 av = make_float4(0.f, 0.f, 0.f, 0.f);
            if (row < MROWS) {
                const float* src;
                if (mode == 0) {
                    int b = row / SS;
                    int s = row - b * SS;
                    src = (s == 0) ? (cls + (size_t)b * CC)
                                   : (x + ((size_t)b * NN + (s - 1)) * CC);
                } else {
                    src = g_attn + (size_t)row * CC;
                }
                av = *(const float4*)(src + k0 + ak);
            }
            As[ak + 0][ar] = av.x; As[ak + 1][ar] = av.y;
            As[ak + 2][ar] = av.z; As[ak + 3][ar] = av.w;
            int col = col0 + ar;
            float4 bv = *(const float4*)(w + (size_t)col * CC + k0 + ak);
            Bs[ak + 0][ar] = bv.x; Bs[ak + 1][ar] = bv.y;
            Bs[ak + 2][ar] = bv.z; Bs[ak + 3][ar] = bv.w;
        }
        __syncthreads();

#pragma unroll
        for (int kk = 0; kk < 16; kk++) {
            float a[8], b[8];
#pragma unroll
            for (int i = 0; i < 8; i++) a[i] = As[kk][ty + 16 * i];
#pragma unroll
            for (int j = 0; j < 8; j++) b[j] = Bs[kk][tx + 16 * j];
#pragma unroll
            for (int i = 0; i < 8; i++)
#pragma unroll
                for (int j = 0; j < 8; j++) acc[i][j] += a[i] * b[j];
        }
        __syncthreads();
    }

    const float QSCALE = 0.17677669529663687f * 1.4426950408889634f;

#pragma unroll
    for (int i = 0; i < 8; i++) {
        int row = row0 + ty + 16 * i;
        if (row >= MROWS) continue;
        int b = row / SS;
        int s = row - b * SS;
#pragma unroll
        for (int j = 0; j < 8; j++) {
            int n = col0 + tx + 16 * j;
            float v = acc[i][j];
            if (mode == 0) {
                int c3  = n >> 8;
                int rem = n & 255;
                int h   = rem >> 5;
                int d   = rem & 31;
                int bh  = b * NH + h;
                if (c3 == 0) {
                    g_q[((size_t)bh * SP + s) * HD + d] = __float2half(v * QSCALE);
                } else if (c3 == 1) {
                    g_k[((size_t)bh * SP + s) * HD + d] = __float2half(v);
                } else {
                    g_vt[((size_t)bh * HD + d) * SP + s] = __float2half(v);
                }
            } else {
                v += bias[n];
                if (s == 0) out_cls[(size_t)b * CC + n] = v;
                else        out_x[((size_t)b * NN + (s - 1)) * CC + n] = v;
            }
        }
    }
}

// ---------------------------------------------------------------------------
// V column sums in exact fp32 via sum_s V[s][d] = (sum_s x_cat[s]) @ Wv^T.
// 4 blocks (one per batch), 1024 threads.
// ---------------------------------------------------------------------------
__global__ __launch_bounds__(1024) void vsum_kernel(
    const float* __restrict__ x, const float* __restrict__ cls,
    const float* __restrict__ qkv_w)
{
    __shared__ float part[4][256];
    __shared__ float xs[256];
    const int b  = blockIdx.x;
    const int t  = threadIdx.x;
    const int c  = t & 255;
    const int st = t >> 8;

    float s = (st == 0) ? cls[(size_t)b * CC + c] : 0.f;
    for (int n = st; n < NN; n += 4)
        s += x[((size_t)b * NN + n) * CC + c];
    part[st][c] = s;
    __syncthreads();

    if (t < 256)
        xs[t] = part[0][t] + part[1][t] + part[2][t] + part[3][t];
    __syncthreads();

    if (t < 256) {
        const float* wr = qkv_w + (size_t)(2 * CC + t) * CC;   // Wv row t
        float acc = 0.f;
#pragma unroll 8
        for (int cc = 0; cc < CC; cc++) acc += xs[cc] * wr[cc];
        int h = t >> 5, d = t & 31;
        g_vsum[(b * NH + h) * HD + d] = acc;
    }
}

// ---------------------------------------------------------------------------
// Flash attention, fp16 mma.sync, mean-subtracted PV:
//   S = q*k (single fp16 term, scale+log2e folded into q)
//   p = exp2(S); f = p-1 (fp16)       l = sum p
//   O = (Vsum + sum f*v) / l
// 256 threads (8 warps), 128 q rows, key tiles of 64, cp.async double buffer.
// ---------------------------------------------------------------------------
#define TKEY 64
#define QTILE 128
#define STK 40                 // K smem row stride (halves): 80B, ldmatrix conflict-free
#define STV 72                 // V^T smem row stride (halves): 144B
#define KT_TILES (SP / TKEY)   // 50

__global__ __launch_bounds__(256, 2) void attn_mma_kernel()
{
    __shared__ alignas(16) uint16_t Kbuf[2][64 * STK];
    __shared__ alignas(16) uint16_t Vbuf[2][32 * STV];

    const int t    = threadIdx.x;
    const int w    = t >> 5;
    const int lane = t & 31;
    const int g    = lane >> 2;
    const int m2   = (lane & 3) * 2;
    const int bh   = blockIdx.y;
    const int q0   = blockIdx.x * QTILE;
    const int qrow = q0 + w * 16;

    // cp.async store slots
    const int kr = t >> 2, kc4 = t & 3;      // K: 64 rows x 4 x 16B
    const int vr = t >> 3, vc8 = t & 7;      // V: 32 rows x 8 x 16B
    const __half* gk = g_k + (size_t)bh * SP * HD;
    const __half* gv = g_vt + (size_t)bh * HD * SP + (size_t)vr * SP;
    uint32_t kdst[2], vdst[2];
    kdst[0] = smem_u32(&Kbuf[0][kr * STK + kc4 * 8]);
    kdst[1] = smem_u32(&Kbuf[1][kr * STK + kc4 * 8]);
    vdst[0] = smem_u32(&Vbuf[0][vr * STV + vc8 * 8]);
    vdst[1] = smem_u32(&Vbuf[1][vr * STV + vc8 * 8]);

    // ldmatrix lane addresses
    uint32_t kmat[2], vmat[2];
    {
        uint32_t ko = ((lane & 7) * STK + (lane >> 3) * 8) * 2;
        uint32_t vo = ((lane & 7) * STV + (lane >> 3) * 8) * 2;
        kmat[0] = smem_u32(Kbuf[0]) + ko; kmat[1] = smem_u32(Kbuf[1]) + ko;
        vmat[0] = smem_u32(Vbuf[0]) + vo; vmat[1] = smem_u32(Vbuf[1]) + vo;
    }

    // Q fragments (rows beyond SS read zero padding; SP bound never exceeded)
    uint32_t qa[2][4];
    {
        const __half* qb = g_q + (size_t)bh * SP * HD;
        int r0 = qrow + g, r1 = qrow + g + 8;
#pragma unroll
        for (int kc = 0; kc < 2; kc++) {
            int d0 = kc * 16 + m2, d1 = d0 + 8;
            qa[kc][0] = *(const uint32_t*)(qb + (size_t)r0 * HD + d0);
            qa[kc][1] = *(const uint32_t*)(qb + (size_t)r1 * HD + d0);
            qa[kc][2] = *(const uint32_t*)(qb + (size_t)r0 * HD + d1);
            qa[kc][3] = *(const uint32_t*)(qb + (size_t)r1 * HD + d1);
        }
    }

    float o[4][4];
#pragma unroll
    for (int i = 0; i < 4; i++)
#pragma unroll
        for (int j = 0; j < 4; j++) o[i][j] = 0.f;
    float la = 0.f, lb = 0.f;

    // prologue: prefetch tile 0
    {
        CP16(kdst[0], gk + (size_t)kr * HD + kc4 * 8);
        CP16(vdst[0], gv + vc8 * 8);
        CPCOMMIT();
    }

    for (int kt = 0; kt < KT_TILES; kt++) {
        const int cur = kt & 1;
        __syncthreads();
        if (kt + 1 < KT_TILES) {
            int nk = kt + 1;
            CP16(kdst[cur ^ 1], gk + (size_t)(nk * TKEY + kr) * HD + kc4 * 8);
            CP16(vdst[cur ^ 1], gv + nk * TKEY + vc8 * 8);
        }
        CPCOMMIT();
        CPWAIT1();
        __syncthreads();

        // ---- S = Q K^T : 8 n-chunks, 1 fp16 term, 2 k-chunks ----
        float sf[8][4];
#pragma unroll
        for (int jn = 0; jn < 8; jn++) {
            uint32_t kb4[4];
            ldm4(kb4, kmat[cur] + jn * (8 * STK * 2));
            sf[jn][0] = sf[jn][1] = sf[jn][2] = sf[jn][3] = 0.f;
            mma16816h(sf[jn], qa[0], kb4 + 0, sf[jn]);
            mma16816h(sf[jn], qa[1], kb4 + 2, sf[jn]);
        }

        // ---- p = exp2(s); f = p-1 packed fp16; accumulate l ----
        uint32_t fh[8][2];
        if (kt < KT_TILES - 1) {
#pragma unroll
            for (int jn = 0; jn < 8; jn++) {
                float p0 = ex2(sf[jn][0]);
                float p1 = ex2(sf[jn][1]);
                float p2 = ex2(sf[jn][2]);
                float p3 = ex2(sf[jn][3]);
                la += p0 + p1;
                lb += p2 + p3;
                fh[jn][0] = packh(p0 - 1.f, p1 - 1.f);
                fh[jn][1] = packh(p2 - 1.f, p3 - 1.f);
            }
        } else {
            const int kb = kt * TKEY;
#pragma unroll
            for (int jn = 0; jn < 8; jn++) {
                int col0 = kb + jn * 8 + m2;
                bool c0v = col0 < SS, c1v = (col0 + 1) < SS;
                float p0 = c0v ? ex2(sf[jn][0]) : 0.f;
                float p1 = c1v ? ex2(sf[jn][1]) : 0.f;
                float p2 = c0v ? ex2(sf[jn][2]) : 0.f;
                float p3 = c1v ? ex2(sf[jn][3]) : 0.f;
                la += p0 + p1;
                lb += p2 + p3;
                fh[jn][0] = packh(c0v ? (p0 - 1.f) : 0.f, c1v ? (p1 - 1.f) : 0.f);
                fh[jn][1] = packh(c0v ? (p2 - 1.f) : 0.f, c1v ? (p3 - 1.f) : 0.f);
            }
        }

        // ---- O += F V : 4 dim-chunks x 4 k-chunks, 1 fp16 term ----
        uint32_t pa[4][4];
#pragma unroll
        for (int kc2 = 0; kc2 < 4; kc2++) {
            pa[kc2][0] = fh[2 * kc2][0];
            pa[kc2][1] = fh[2 * kc2][1];
            pa[kc2][2] = fh[2 * kc2 + 1][0];
            pa[kc2][3] = fh[2 * kc2 + 1][1];
        }
#pragma unroll
        for (int jn2 = 0; jn2 < 4; jn2++) {
            uint32_t vv[8];
            ldm4(vv,     vmat[cur] + jn2 * (8 * STV * 2));
            ldm4(vv + 4, vmat[cur] + jn2 * (8 * STV * 2) + 64);
#pragma unroll
            for (int kc2 = 0; kc2 < 4; kc2++)
                mma16816h(o[jn2], pa[kc2], vv + 2 * kc2, o[jn2]);
        }
    }

    // ---- reduce l over quad, add Vsum, normalize, store ----
    la += __shfl_xor_sync(0xffffffffu, la, 1);
    la += __shfl_xor_sync(0xffffffffu, la, 2);
    lb += __shfl_xor_sync(0xffffffffu, lb, 1);
    lb += __shfl_xor_sync(0xffffffffu, lb, 2);
    const float ia = 1.f / la, ib = 1.f / lb;

    const int b = bh >> 3;
    const int h = bh & 7;
    const int r0 = qrow + g, r1 = qrow + g + 8;
#pragma unroll
    for (int jn2 = 0; jn2 < 4; jn2++) {
        float2 vs = *(const float2*)&g_vsum[bh * HD + jn2 * 8 + m2];
        if (r0 < SS) {
            float* dst = g_attn + ((size_t)b * SS + r0) * CC + h * HD + jn2 * 8 + m2;
            *(float2*)dst = make_float2((o[jn2][0] + vs.x) * ia,
                                        (o[jn2][1] + vs.y) * ia);
        }
        if (r1 < SS) {
            float* dst = g_attn + ((size_t)b * SS + r1) * CC + h * HD + jn2 * 8 + m2;
            *(float2*)dst = make_float2((o[jn2][2] + vs.x) * ib,
                                        (o[jn2][3] + vs.y) * ib);
        }
    }
}

// ---------------------------------------------------------------------------
// LePE: 5x5 depthwise conv (SAME) over x (NHWC), added in place into g_attn
// ---------------------------------------------------------------------------
__global__ __launch_bounds__(256) void lepe_kernel(
    const float* __restrict__ x, const float* __restrict__ lw,
    const float* __restrict__ lb)
{
    __shared__ float wsh[CC][25];
    const int c  = threadIdx.x;
    const int xw = blockIdx.x;
    const int yh = blockIdx.y;
    const int b  = blockIdx.z;

    for (int i = c; i < CC * 25; i += 256) {
        wsh[i / 25][i % 25] = lw[i];
    }
    __syncthreads();

    float sum = lb[c];
#pragma unroll
    for (int ky = 0; ky < 5; ky++) {
        int yy = yh + ky - 2;
        if (yy < 0 || yy >= HH) continue;
#pragma unroll
        for (int kx = 0; kx < 5; kx++) {
            int xx = xw + kx - 2;
            if (xx < 0 || xx >= WW) continue;
            sum += x[(((size_t)b * HH + yy) * WW + xx) * CC + c] * wsh[c][ky * 5 + kx];
        }
    }
    g_attn[((size_t)b * SS + 1 + yh * WW + xw) * CC + c] += sum;
}

// ---------------------------------------------------------------------------
extern "C" void kernel_launch(void* const* d_in, const int* in_sizes, int n_in,
                              void* d_out, int out_size)
{
    const float* x      = (const float*)d_in[0];
    const float* cls    = (const float*)d_in[1];
    const float* qkv_w  = (const float*)d_in[2];
    const float* proj_w = (const float*)d_in[3];
    const float* proj_b = (const float*)d_in[4];
    const float* lepe_w = (const float*)d_in[5];
    const float* lepe_b = (const float*)d_in[6];

    float* out_x   = (float*)d_out;
    float* out_cls = (float*)d_out + in_sizes[0];

    // 0) exact fp32 V column sums (independent of the QKV gemm)
    vsum_kernel<<<BB, 1024>>>(x, cls, qkv_w);

    // 1) QKV projection -> fp16 Q (pre-scaled), K, transposed V
    gemm_kernel<<<dim3((MROWS + 127) / 128, 768 / 128), 256>>>(
        x, cls, qkv_w, nullptr, nullptr, nullptr, 0);

    // 2) fp16 mma.sync flash attention (mean-subtracted PV)
    attn_mma_kernel<<<dim3((SS + QTILE - 1) / QTILE, BHN), 256>>>();

    // 3) LePE depthwise conv added into g_attn
    lepe_kernel<<<dim3(WW, HH, BB), 256>>>(x, lepe_w, lepe_b);

    // 4) Output projection
    gemm_kernel<<<dim3((MROWS + 127) / 128, CC / 128), 256>>>(
        nullptr, nullptr, proj_w, proj_b, out_x, out_cls, 1);
}

// round 9
// speedup vs baseline: 3.4779x; 1.0189x over previous
#include <cuda_runtime.h>
#include <cuda_fp16.h>
#include <cstdint>

// Problem constants
#define BB   4
#define HH   56
#define WW   56
#define CC   256
#define NH   8
#define HD   32
#define NN   (HH*WW)          // 3136
#define SS   (NN + 1)         // 3137
#define SP   3200             // padded seq stride (25*128 exactly)
#define MROWS (BB * SS)       // 12548
#define BHN  (BB * NH)        // 32

// Scratch (device globals; zero-initialized — padding stays 0)
__device__ float g_attn[(size_t)BB * SS * CC];
__device__ __half g_q[(size_t)BHN * SP * HD];    // pre-scaled by 1/sqrt(hd)*log2(e)
__device__ __half g_k[(size_t)BHN * SP * HD];
__device__ __half g_vt[(size_t)BHN * HD * SP];   // V^T: [bh][d][s]
__device__ float  g_vsum[BB * CC];               // fp32 exact sum_s V[s][d] (b,h,d)
__device__ float  g_xpart[64][CC];               // partial column sums of x

// ---------------------------------------------------------------------------
// PTX helpers (baseline-PTX instructions only: sm_80/75 features, OK at sm_103)
// ---------------------------------------------------------------------------
__device__ __forceinline__ uint32_t smem_u32(const void* p) {
    uint32_t a;
    asm("{ .reg .u64 t; cvta.to.shared.u64 t, %1; cvt.u32.u64 %0, t; }"
        : "=r"(a) : "l"(p));
    return a;
}
__device__ __forceinline__ void mma16816h(float* d, const uint32_t* a,
                                          const uint32_t* b, const float* c) {
    asm volatile(
        "mma.sync.aligned.m16n8k16.row.col.f32.f16.f16.f32 "
        "{%0,%1,%2,%3}, {%4,%5,%6,%7}, {%8,%9}, {%10,%11,%12,%13};"
        : "=f"(d[0]), "=f"(d[1]), "=f"(d[2]), "=f"(d[3])
        : "r"(a[0]), "r"(a[1]), "r"(a[2]), "r"(a[3]),
          "r"(b[0]), "r"(b[1]),
          "f"(c[0]), "f"(c[1]), "f"(c[2]), "f"(c[3]));
}
__device__ __forceinline__ void ldm4(uint32_t* r, uint32_t a) {
    asm volatile("ldmatrix.sync.aligned.m8n8.x4.shared.b16 {%0,%1,%2,%3}, [%4];"
                 : "=r"(r[0]), "=r"(r[1]), "=r"(r[2]), "=r"(r[3]) : "r"(a));
}
__device__ __forceinline__ float ex2(float x) {
    float r;
    asm("ex2.approx.ftz.f32 %0, %1;" : "=f"(r) : "f"(x));
    return r;
}
// pack two f32 -> f16x2 (lo half = first arg)
__device__ __forceinline__ uint32_t packh(float lo, float hi) {
    uint32_t r;
    asm("cvt.rn.f16x2.f32 %0, %1, %2;" : "=r"(r) : "f"(hi), "f"(lo));
    return r;
}
__device__ __forceinline__ uint32_t ex2h2(uint32_t s) {
    uint32_t r;
    asm("ex2.approx.f16x2 %0, %1;" : "=r"(r) : "r"(s));
    return r;
}
__device__ __forceinline__ uint32_t hsub2u(uint32_t a, uint32_t b) {
    uint32_t r;
    asm("sub.rn.f16x2 %0, %1, %2;" : "=r"(r) : "r"(a), "r"(b));
    return r;
}
__device__ __forceinline__ uint32_t hadd2u(uint32_t a, uint32_t b) {
    uint32_t r;
    asm("add.rn.f16x2 %0, %1, %2;" : "=r"(r) : "r"(a), "r"(b));
    return r;
}
#define CP16(dst, src) asm volatile("cp.async.cg.shared.global [%0], [%1], 16;" :: "r"(dst), "l"(src) : "memory")
#define CPCOMMIT()     asm volatile("cp.async.commit_group;" ::: "memory")
#define CPWAIT1()      asm volatile("cp.async.wait_group 1;" ::: "memory")

// ---------------------------------------------------------------------------
// Unified tiled GEMM: C[M,N] = A[M,256] * W[N,256]^T (+bias)
// mode 0: A = concat(cls, x); outputs fp16 Q (pre-scaled), K, V^T
// mode 1: A = g_attn; outputs -> d_out (x part / cls part) with bias
// ---------------------------------------------------------------------------
__global__ __launch_bounds__(256) void gemm_kernel(
    const float* __restrict__ x, const float* __restrict__ cls,
    const float* __restrict__ w, const float* __restrict__ bias,
    float* __restrict__ out_x, float* __restrict__ out_cls, int mode)
{
    __shared__ float As[16][132];
    __shared__ float Bs[16][132];

    const int t    = threadIdx.x;
    const int row0 = blockIdx.x * 128;
    const int col0 = blockIdx.y * 128;
    const int ty   = t >> 4;
    const int tx   = t & 15;

    float acc[8][8];
#pragma unroll
    for (int i = 0; i < 8; i++)
#pragma unroll
        for (int j = 0; j < 8; j++) acc[i][j] = 0.f;

    for (int k0 = 0; k0 < 256; k0 += 16) {
#pragma unroll
        for (int lp = 0; lp < 2; lp++) {
            int f  = t + lp * 256;
            int ar = f >> 2;
            int ak = (f & 3) << 2;
            int row = row0 + ar;
            float4 av = make_float4(0.f, 0.f, 0.f, 0.f);
            if (row < MROWS) {
                const float* src;
                if (mode == 0) {
                    int b = row / SS;
                    int s = row - b * SS;
                    src = (s == 0) ? (cls + (size_t)b * CC)
                                   : (x + ((size_t)b * NN + (s - 1)) * CC);
                } else {
                    src = g_attn + (size_t)row * CC;
                }
                av = *(const float4*)(src + k0 + ak);
            }
            As[ak + 0][ar] = av.x; As[ak + 1][ar] = av.y;
            As[ak + 2][ar] = av.z; As[ak + 3][ar] = av.w;
            int col = col0 + ar;
            float4 bv = *(const float4*)(w + (size_t)col * CC + k0 + ak);
            Bs[ak + 0][ar] = bv.x; Bs[ak + 1][ar] = bv.y;
            Bs[ak + 2][ar] = bv.z; Bs[ak + 3][ar] = bv.w;
        }
        __syncthreads();

#pragma unroll
        for (int kk = 0; kk < 16; kk++) {
            float a[8], b[8];
#pragma unroll
            for (int i = 0; i < 8; i++) a[i] = As[kk][ty + 16 * i];
#pragma unroll
            for (int j = 0; j < 8; j++) b[j] = Bs[kk][tx + 16 * j];
#pragma unroll
            for (int i = 0; i < 8; i++)
#pragma unroll
                for (int j = 0; j < 8; j++) acc[i][j] += a[i] * b[j];
        }
        __syncthreads();
    }

    const float QSCALE = 0.17677669529663687f * 1.4426950408889634f;

#pragma unroll
    for (int i = 0; i < 8; i++) {
        int row = row0 + ty + 16 * i;
        if (row >= MROWS) continue;
        int b = row / SS;
        int s = row - b * SS;
#pragma unroll
        for (int j = 0; j < 8; j++) {
            int n = col0 + tx + 16 * j;
            float v = acc[i][j];
            if (mode == 0) {
                int c3  = n >> 8;
                int rem = n & 255;
                int h   = rem >> 5;
                int d   = rem & 31;
                int bh  = b * NH + h;
                if (c3 == 0) {
                    g_q[((size_t)bh * SP + s) * HD + d] = __float2half(v * QSCALE);
                } else if (c3 == 1) {
                    g_k[((size_t)bh * SP + s) * HD + d] = __float2half(v);
                } else {
                    g_vt[((size_t)bh * HD + d) * SP + s] = __float2half(v);
                }
            } else {
                v += bias[n];
                if (s == 0) out_cls[(size_t)b * CC + n] = v;
                else        out_x[((size_t)b * NN + (s - 1)) * CC + n] = v;
            }
        }
    }
}

// ---------------------------------------------------------------------------
// V column sums, two-stage:
//  a) 64 blocks: partial column sums of x (196 rows each)
//  b) 4 blocks: reduce partials + cls, multiply by Wv^T row -> g_vsum
// ---------------------------------------------------------------------------
__global__ __launch_bounds__(256) void vsum_a_kernel(const float* __restrict__ x)
{
    const int blk = blockIdx.x;          // b*16 + chunk
    const int b   = blk >> 4, ch = blk & 15;
    const int c   = threadIdx.x;
    const float* p = x + ((size_t)b * NN + ch * 196) * CC + c;
    float s = 0.f;
#pragma unroll 4
    for (int r = 0; r < 196; r++) s += p[(size_t)r * CC];
    g_xpart[blk][c] = s;
}

__global__ __launch_bounds__(256) void vsum_b_kernel(
    const float* __restrict__ cls, const float* __restrict__ qkv_w)
{
    __shared__ float xs[256];
    const int b = blockIdx.x;
    const int t = threadIdx.x;
    float s = cls[b * CC + t];
#pragma unroll
    for (int k = 0; k < 16; k++) s += g_xpart[b * 16 + k][t];
    xs[t] = s;
    __syncthreads();
    const float* wr = qkv_w + (size_t)(2 * CC + t) * CC;   // Wv row t
    float acc = 0.f;
#pragma unroll 8
    for (int cc = 0; cc < CC; cc++) acc += xs[cc] * wr[cc];
    g_vsum[b * CC + t] = acc;    // (b, h, d) contiguous == b*256 + t
}

// ---------------------------------------------------------------------------
// Flash attention, fp16 mma.sync, mean-subtracted PV:
//   S = q*k (single fp16 term, scale+log2e folded into q)
//   p = exp2(S) via f16x2 MUFU; f = p-1 (f16x2)   l = sum p (f16x2 tree + f32)
//   O = (Vsum + sum f*v) / l
// 256 threads (8 warps), 128 q rows, key tiles of 64, cp.async double buffer.
// ---------------------------------------------------------------------------
#define TKEY 64
#define QTILE 128
#define STK 40                 // K smem row stride (halves): 80B, ldmatrix conflict-free
#define STV 72                 // V^T smem row stride (halves): 144B
#define KT_TILES (SP / TKEY)   // 50

__global__ __launch_bounds__(256, 2) void attn_mma_kernel()
{
    __shared__ alignas(16) uint16_t Kbuf[2][64 * STK];
    __shared__ alignas(16) uint16_t Vbuf[2][32 * STV];

    const int t    = threadIdx.x;
    const int w    = t >> 5;
    const int lane = t & 31;
    const int g    = lane >> 2;
    const int m2   = (lane & 3) * 2;
    const int bh   = blockIdx.y;
    const int q0   = blockIdx.x * QTILE;
    const int qrow = q0 + w * 16;

    // cp.async store slots
    const int kr = t >> 2, kc4 = t & 3;      // K: 64 rows x 4 x 16B
    const int vr = t >> 3, vc8 = t & 7;      // V: 32 rows x 8 x 16B
    const __half* gk = g_k + (size_t)bh * SP * HD;
    const __half* gv = g_vt + (size_t)bh * HD * SP + (size_t)vr * SP;
    uint32_t kdst[2], vdst[2];
    kdst[0] = smem_u32(&Kbuf[0][kr * STK + kc4 * 8]);
    kdst[1] = smem_u32(&Kbuf[1][kr * STK + kc4 * 8]);
    vdst[0] = smem_u32(&Vbuf[0][vr * STV + vc8 * 8]);
    vdst[1] = smem_u32(&Vbuf[1][vr * STV + vc8 * 8]);

    // ldmatrix lane addresses
    uint32_t kmat[2], vmat[2];
    {
        uint32_t ko = ((lane & 7) * STK + (lane >> 3) * 8) * 2;
        uint32_t vo = ((lane & 7) * STV + (lane >> 3) * 8) * 2;
        kmat[0] = smem_u32(Kbuf[0]) + ko; kmat[1] = smem_u32(Kbuf[1]) + ko;
        vmat[0] = smem_u32(Vbuf[0]) + vo; vmat[1] = smem_u32(Vbuf[1]) + vo;
    }

    // Q fragments (rows beyond SS read zero padding; SP bound never exceeded)
    uint32_t qa[2][4];
    {
        const __half* qb = g_q + (size_t)bh * SP * HD;
        int r0 = qrow + g, r1 = qrow + g + 8;
#pragma unroll
        for (int kc = 0; kc < 2; kc++) {
            int d0 = kc * 16 + m2, d1 = d0 + 8;
            qa[kc][0] = *(const uint32_t*)(qb + (size_t)r0 * HD + d0);
            qa[kc][1] = *(const uint32_t*)(qb + (size_t)r1 * HD + d0);
            qa[kc][2] = *(const uint32_t*)(qb + (size_t)r0 * HD + d1);
            qa[kc][3] = *(const uint32_t*)(qb + (size_t)r1 * HD + d1);
        }
    }

    float o[4][4];
#pragma unroll
    for (int i = 0; i < 4; i++)
#pragma unroll
        for (int j = 0; j < 4; j++) o[i][j] = 0.f;
    float la = 0.f, lb = 0.f;
    const uint32_t ONE2 = 0x3C003C00u;   // half2(1, 1)

    // prologue: prefetch tile 0
    {
        CP16(kdst[0], gk + (size_t)kr * HD + kc4 * 8);
        CP16(vdst[0], gv + vc8 * 8);
        CPCOMMIT();
    }

    for (int kt = 0; kt < KT_TILES; kt++) {
        const int cur = kt & 1;
        __syncthreads();
        if (kt + 1 < KT_TILES) {
            int nk = kt + 1;
            CP16(kdst[cur ^ 1], gk + (size_t)(nk * TKEY + kr) * HD + kc4 * 8);
            CP16(vdst[cur ^ 1], gv + nk * TKEY + vc8 * 8);
        }
        CPCOMMIT();
        CPWAIT1();
        __syncthreads();

        // ---- S = Q K^T : 8 n-chunks, 1 fp16 term, 2 k-chunks ----
        float sf[8][4];
#pragma unroll
        for (int jn = 0; jn < 8; jn++) {
            uint32_t kb4[4];
            ldm4(kb4, kmat[cur] + jn * (8 * STK * 2));
            sf[jn][0] = sf[jn][1] = sf[jn][2] = sf[jn][3] = 0.f;
            mma16816h(sf[jn], qa[0], kb4 + 0, sf[jn]);
            mma16816h(sf[jn], qa[1], kb4 + 2, sf[jn]);
        }

        // ---- p = exp2(s) (f16x2 MUFU); f = p-1; l via f16x2 tree ----
        uint32_t fh[8][2];
        if (kt < KT_TILES - 1) {
            uint32_t t01[8], t23[8];
#pragma unroll
            for (int jn = 0; jn < 8; jn++) {
                uint32_t p01 = ex2h2(packh(sf[jn][0], sf[jn][1]));
                uint32_t p23 = ex2h2(packh(sf[jn][2], sf[jn][3]));
                fh[jn][0] = hsub2u(p01, ONE2);
                fh[jn][1] = hsub2u(p23, ONE2);
                t01[jn] = p01; t23[jn] = p23;
            }
            uint32_t a0 = hadd2u(hadd2u(t01[0], t01[1]), hadd2u(t01[2], t01[3]));
            uint32_t a1 = hadd2u(hadd2u(t01[4], t01[5]), hadd2u(t01[6], t01[7]));
            uint32_t b0 = hadd2u(hadd2u(t23[0], t23[1]), hadd2u(t23[2], t23[3]));
            uint32_t b1 = hadd2u(hadd2u(t23[4], t23[5]), hadd2u(t23[6], t23[7]));
            a0 = hadd2u(a0, a1);
            b0 = hadd2u(b0, b1);
            __half2 ha = *(__half2*)&a0;
            __half2 hb = *(__half2*)&b0;
            la += __low2float(ha) + __high2float(ha);
            lb += __low2float(hb) + __high2float(hb);
        } else {
            // last tile: exact scalar path with column masking
            const int kb = kt * TKEY;
#pragma unroll
            for (int jn = 0; jn < 8; jn++) {
                int col0 = kb + jn * 8 + m2;
                bool c0v = col0 < SS, c1v = (col0 + 1) < SS;
                float p0 = c0v ? ex2(sf[jn][0]) : 0.f;
                float p1 = c1v ? ex2(sf[jn][1]) : 0.f;
                float p2 = c0v ? ex2(sf[jn][2]) : 0.f;
                float p3 = c1v ? ex2(sf[jn][3]) : 0.f;
                la += p0 + p1;
                lb += p2 + p3;
                fh[jn][0] = packh(c0v ? (p0 - 1.f) : 0.f, c1v ? (p1 - 1.f) : 0.f);
                fh[jn][1] = packh(c0v ? (p2 - 1.f) : 0.f, c1v ? (p3 - 1.f) : 0.f);
            }
        }

        // ---- O += F V : 4 dim-chunks x 4 k-chunks, 1 fp16 term ----
        uint32_t pa[4][4];
#pragma unroll
        for (int kc2 = 0; kc2 < 4; kc2++) {
            pa[kc2][0] = fh[2 * kc2][0];
            pa[kc2][1] = fh[2 * kc2][1];
            pa[kc2][2] = fh[2 * kc2 + 1][0];
            pa[kc2][3] = fh[2 * kc2 + 1][1];
        }
#pragma unroll
        for (int jn2 = 0; jn2 < 4; jn2++) {
            uint32_t vv[8];
            ldm4(vv,     vmat[cur] + jn2 * (8 * STV * 2));
            ldm4(vv + 4, vmat[cur] + jn2 * (8 * STV * 2) + 64);
#pragma unroll
            for (int kc2 = 0; kc2 < 4; kc2++)
                mma16816h(o[jn2], pa[kc2], vv + 2 * kc2, o[jn2]);
        }
    }

    // ---- reduce l over quad, add Vsum, normalize, store ----
    la += __shfl_xor_sync(0xffffffffu, la, 1);
    la += __shfl_xor_sync(0xffffffffu, la, 2);
    lb += __shfl_xor_sync(0xffffffffu, lb, 1);
    lb += __shfl_xor_sync(0xffffffffu, lb, 2);
    const float ia = 1.f / la, ib = 1.f / lb;

    const int b = bh >> 3;
    const int h = bh & 7;
    const int r0 = qrow + g, r1 = qrow + g + 8;
#pragma unroll
    for (int jn2 = 0; jn2 < 4; jn2++) {
        float2 vs = *(const float2*)&g_vsum[b * CC + h * HD + jn2 * 8 + m2];
        if (r0 < SS) {
            float* dst = g_attn + ((size_t)b * SS + r0) * CC + h * HD + jn2 * 8 + m2;
            *(float2*)dst = make_float2((o[jn2][0] + vs.x) * ia,
                                        (o[jn2][1] + vs.y) * ia);
        }
        if (r1 < SS) {
            float* dst = g_attn + ((size_t)b * SS + r1) * CC + h * HD + jn2 * 8 + m2;
            *(float2*)dst = make_float2((o[jn2][2] + vs.x) * ib,
                                        (o[jn2][3] + vs.y) * ib);
        }
    }
}

// ---------------------------------------------------------------------------
// LePE: 5x5 depthwise conv (SAME), sliding-window version.
// Block = (14-px x-group, y, b), 256 threads = channels.
// Weights in registers; 5-column rolling window in registers.
// ---------------------------------------------------------------------------
#define XG 14
__global__ __launch_bounds__(256) void lepe_kernel(
    const float* __restrict__ x, const float* __restrict__ lw,
    const float* __restrict__ lb)
{
    __shared__ float wsh[25][256];
    const int c  = threadIdx.x;
    const int x0 = blockIdx.x * XG;
    const int y  = blockIdx.y;
    const int b  = blockIdx.z;

    // coalesced weight stage, then to registers
    for (int i = c; i < 25 * 256; i += 256)
        wsh[i % 25][i / 25] = lw[i];
    __syncthreads();
    float wt[25];
#pragma unroll
    for (int k = 0; k < 25; k++) wt[k] = wsh[k][c];
    const float lbv = lb[c];

    const float* xb = x + (size_t)b * HH * WW * CC + c;
    bool rv[5];
#pragma unroll
    for (int ky = 0; ky < 5; ky++) rv[ky] = (unsigned)(y + ky - 2) < (unsigned)HH;

    float win[5][5];   // [col slot][ky]
#pragma unroll
    for (int j = 0; j < 4; j++) {
        int col = x0 + j - 2;
        bool cv = (unsigned)col < (unsigned)WW;
#pragma unroll
        for (int ky = 0; ky < 5; ky++)
            win[j][ky] = (cv && rv[ky])
                ? xb[((size_t)(y + ky - 2) * WW + col) * CC] : 0.f;
    }

#pragma unroll
    for (int i = 0; i < XG; i++) {
        const int slot = (i + 4) % 5;
        int col = x0 + i + 2;
        bool cv = col < WW;
#pragma unroll
        for (int ky = 0; ky < 5; ky++)
            win[slot][ky] = (cv && rv[ky])
                ? xb[((size_t)(y + ky - 2) * WW + col) * CC] : 0.f;

        float sum = lbv;
#pragma unroll
        for (int kx = 0; kx < 5; kx++) {
            const int s = (i + kx) % 5;
#pragma unroll
            for (int ky = 0; ky < 5; ky++)
                sum += win[s][ky] * wt[ky * 5 + kx];
        }
        g_attn[((size_t)b * SS + 1 + y * WW + x0 + i) * CC + c] += sum;
    }
}

// ---------------------------------------------------------------------------
extern "C" void kernel_launch(void* const* d_in, const int* in_sizes, int n_in,
                              void* d_out, int out_size)
{
    const float* x      = (const float*)d_in[0];
    const float* cls    = (const float*)d_in[1];
    const float* qkv_w  = (const float*)d_in[2];
    const float* proj_w = (const float*)d_in[3];
    const float* proj_b = (const float*)d_in[4];
    const float* lepe_w = (const float*)d_in[5];
    const float* lepe_b = (const float*)d_in[6];

    float* out_x   = (float*)d_out;
    float* out_cls = (float*)d_out + in_sizes[0];

    // 0) exact fp32 V column sums (two-stage, wide)
    vsum_a_kernel<<<64, 256>>>(x);
    vsum_b_kernel<<<BB, 256>>>(cls, qkv_w);

    // 1) QKV projection -> fp16 Q (pre-scaled), K, transposed V
    gemm_kernel<<<dim3((MROWS + 127) / 128, 768 / 128), 256>>>(
        x, cls, qkv_w, nullptr, nullptr, nullptr, 0);

    // 2) fp16 mma.sync flash attention (mean-subtracted PV, f16x2 epilogue)
    attn_mma_kernel<<<dim3((SS + QTILE - 1) / QTILE, BHN), 256>>>();

    // 3) LePE depthwise conv added into g_attn (sliding window)
    lepe_kernel<<<dim3(WW / XG, HH, BB), 256>>>(x, lepe_w, lepe_b);

    // 4) Output projection
    gemm_kernel<<<dim3((MROWS + 127) / 128, CC / 128), 256>>>(
        nullptr, nullptr, proj_w, proj_b, out_x, out_cls, 1);
}

// round 10
// speedup vs baseline: 5.6175x; 1.6152x over previous
#include <cuda_runtime.h>
#include <cuda_fp16.h>
#include <cstdint>

// Problem constants
#define BB   4
#define HH   56
#define WW   56
#define CC   256
#define NH   8
#define HD   32
#define NN   (HH*WW)          // 3136
#define SS   (NN + 1)         // 3137
#define SP   3200             // padded seq stride (25*128 exactly)
#define MROWS (BB * SS)       // 12548
#define BHN  (BB * NH)        // 32

// Scratch (device globals; zero-initialized — padding stays 0)
__device__ float g_attn[(size_t)BB * SS * CC];
__device__ __half g_q[(size_t)BHN * SP * HD];    // pre-scaled by 1/sqrt(hd)*log2(e)
__device__ __half g_k[(size_t)BHN * SP * HD];
__device__ __half g_vt[(size_t)BHN * HD * SP];   // V^T: [bh][d][s]
__device__ float  g_vsum[BB * CC];               // fp32 exact sum_s V[s][d] (b,h,d)
__device__ float  g_xpart[256][CC];              // partial column sums of x

// ---------------------------------------------------------------------------
// PTX helpers (baseline-PTX instructions only)
// ---------------------------------------------------------------------------
__device__ __forceinline__ uint32_t smem_u32(const void* p) {
    uint32_t a;
    asm("{ .reg .u64 t; cvta.to.shared.u64 t, %1; cvt.u32.u64 %0, t; }"
        : "=r"(a) : "l"(p));
    return a;
}
__device__ __forceinline__ void mma16816h(float* d, const uint32_t* a,
                                          const uint32_t* b, const float* c) {
    asm volatile(
        "mma.sync.aligned.m16n8k16.row.col.f32.f16.f16.f32 "
        "{%0,%1,%2,%3}, {%4,%5,%6,%7}, {%8,%9}, {%10,%11,%12,%13};"
        : "=f"(d[0]), "=f"(d[1]), "=f"(d[2]), "=f"(d[3])
        : "r"(a[0]), "r"(a[1]), "r"(a[2]), "r"(a[3]),
          "r"(b[0]), "r"(b[1]),
          "f"(c[0]), "f"(c[1]), "f"(c[2]), "f"(c[3]));
}
__device__ __forceinline__ void ldm4(uint32_t* r, uint32_t a) {
    asm volatile("ldmatrix.sync.aligned.m8n8.x4.shared.b16 {%0,%1,%2,%3}, [%4];"
                 : "=r"(r[0]), "=r"(r[1]), "=r"(r[2]), "=r"(r[3]) : "r"(a));
}
__device__ __forceinline__ float ex2(float x) {
    float r;
    asm("ex2.approx.ftz.f32 %0, %1;" : "=f"(r) : "f"(x));
    return r;
}
// pack two f32 -> f16x2 (lo half = first arg)
__device__ __forceinline__ uint32_t packh(float lo, float hi) {
    uint32_t r;
    asm("cvt.rn.f16x2.f32 %0, %1, %2;" : "=r"(r) : "f"(hi), "f"(lo));
    return r;
}
__device__ __forceinline__ uint32_t ex2h2(uint32_t s) {
    uint32_t r;
    asm("ex2.approx.f16x2 %0, %1;" : "=r"(r) : "r"(s));
    return r;
}
__device__ __forceinline__ uint32_t hsub2u(uint32_t a, uint32_t b) {
    uint32_t r;
    asm("sub.rn.f16x2 %0, %1, %2;" : "=r"(r) : "r"(a), "r"(b));
    return r;
}
__device__ __forceinline__ uint32_t hadd2u(uint32_t a, uint32_t b) {
    uint32_t r;
    asm("add.rn.f16x2 %0, %1, %2;" : "=r"(r) : "r"(a), "r"(b));
    return r;
}
#define CP16(dst, src) asm volatile("cp.async.cg.shared.global [%0], [%1], 16;" :: "r"(dst), "l"(src) : "memory")
#define CPCOMMIT()     asm volatile("cp.async.commit_group;" ::: "memory")
#define CPWAIT1()      asm volatile("cp.async.wait_group 1;" ::: "memory")

// ---------------------------------------------------------------------------
// fp16 tensor-core GEMM: C[M,N] = A[M,256] * W[N,256]^T (+bias)
// Block tile 128x128, 8 warps of 32x64. K staged 32/iter, fp32->fp16 in regs.
// mode 0: A = concat(cls, x); outputs fp16 Q (pre-scaled), K, V^T
// mode 1: A = g_attn; outputs -> d_out (x part / cls part) with bias
// ---------------------------------------------------------------------------
#define STA 40    // smem row stride in halves (80B) — ldmatrix conflict-free
__global__ __launch_bounds__(256, 2) void hgemm_kernel(
    const float* __restrict__ x, const float* __restrict__ cls,
    const float* __restrict__ w, const float* __restrict__ bias,
    float* __restrict__ out_x, float* __restrict__ out_cls, int mode)
{
    __shared__ alignas(16) uint16_t As[128 * STA];
    __shared__ alignas(16) uint16_t Bs[128 * STA];

    const int t    = threadIdx.x;
    const int wp   = t >> 5, lane = t & 31;
    const int wy   = wp >> 1, wx = wp & 1;
    const int g    = lane >> 2, m2 = (lane & 3) * 2;
    const int row0 = blockIdx.x * 128;
    const int col0 = blockIdx.y * 128;

    // staging: thread t handles row t>>1, 16-col half (t&1)
    const int sr = t >> 1;
    const int sc = (t & 1) * 16;

    const float* asrc = nullptr;
    {
        int arow = row0 + sr;
        if (arow < MROWS) {
            if (mode == 0) {
                int ab = arow / SS, asq = arow - ab * SS;
                asrc = (asq == 0) ? (cls + (size_t)ab * CC)
                                  : (x + ((size_t)ab * NN + (asq - 1)) * CC);
            } else {
                asrc = g_attn + (size_t)arow * CC;
            }
        }
    }
    const float* bsrc = w + (size_t)(col0 + sr) * CC + sc;

    // ldmatrix base addresses
    const uint32_t aaddr0 = smem_u32(As)
        + (uint32_t)(wy * 32 + (lane & 15)) * (STA * 2) + (lane >> 4) * 16;
    const uint32_t baddr0 = smem_u32(Bs)
        + (uint32_t)(wx * 64 + (lane & 7)) * (STA * 2) + (lane >> 3) * 16;

    float acc[2][8][4];
#pragma unroll
    for (int f = 0; f < 2; f++)
#pragma unroll
        for (int j = 0; j < 8; j++)
#pragma unroll
            for (int c = 0; c < 4; c++) acc[f][j][c] = 0.f;

    float4 abuf[4], bbuf[4];
    // prologue: load stage 0
#pragma unroll
    for (int q = 0; q < 4; q++) {
        abuf[q] = asrc ? *(const float4*)(asrc + sc + q * 4)
                       : make_float4(0.f, 0.f, 0.f, 0.f);
        bbuf[q] = *(const float4*)(bsrc + q * 4);
    }

    uint16_t* ap = As + sr * STA + sc;
    uint16_t* bp = Bs + sr * STA + sc;

    for (int st = 0; st < 8; st++) {
        // convert + store current stage
        {
            uint4 u0 = make_uint4(packh(abuf[0].x, abuf[0].y), packh(abuf[0].z, abuf[0].w),
                                  packh(abuf[1].x, abuf[1].y), packh(abuf[1].z, abuf[1].w));
            uint4 u1 = make_uint4(packh(abuf[2].x, abuf[2].y), packh(abuf[2].z, abuf[2].w),
                                  packh(abuf[3].x, abuf[3].y), packh(abuf[3].z, abuf[3].w));
            *(uint4*)ap = u0; *(uint4*)(ap + 8) = u1;
            uint4 v0 = make_uint4(packh(bbuf[0].x, bbuf[0].y), packh(bbuf[0].z, bbuf[0].w),
                                  packh(bbuf[1].x, bbuf[1].y), packh(bbuf[1].z, bbuf[1].w));
            uint4 v1 = make_uint4(packh(bbuf[2].x, bbuf[2].y), packh(bbuf[2].z, bbuf[2].w),
                                  packh(bbuf[3].x, bbuf[3].y), packh(bbuf[3].z, bbuf[3].w));
            *(uint4*)bp = v0; *(uint4*)(bp + 8) = v1;
        }
        __syncthreads();

        // prefetch next stage (overlaps MMA)
        if (st < 7) {
            int off = (st + 1) * 32 + sc;
#pragma unroll
            for (int q = 0; q < 4; q++) {
                abuf[q] = asrc ? *(const float4*)(asrc + off + q * 4)
                               : make_float4(0.f, 0.f, 0.f, 0.f);
                bbuf[q] = *(const float4*)(bsrc + (st + 1) * 32 + q * 4);
            }
        }

        // MMA: 2 M-frags x 2 k-chunks x 8 n-chunks
        uint32_t af[2][2][4];
#pragma unroll
        for (int f = 0; f < 2; f++)
#pragma unroll
            for (int c = 0; c < 2; c++)
                ldm4(af[f][c], aaddr0 + f * (16 * STA * 2) + c * 32);
#pragma unroll
        for (int jn = 0; jn < 8; jn++) {
            uint32_t bf[4];
            ldm4(bf, baddr0 + jn * (8 * STA * 2));
            mma16816h(acc[0][jn], af[0][0], bf + 0, acc[0][jn]);
            mma16816h(acc[0][jn], af[0][1], bf + 2, acc[0][jn]);
            mma16816h(acc[1][jn], af[1][0], bf + 0, acc[1][jn]);
            mma16816h(acc[1][jn], af[1][1], bf + 2, acc[1][jn]);
        }
        __syncthreads();
    }

    // epilogue
    const float QSCALE = 0.17677669529663687f * 1.4426950408889634f;
#pragma unroll
    for (int f = 0; f < 2; f++) {
#pragma unroll
        for (int half = 0; half < 2; half++) {
            int row = row0 + wy * 32 + f * 16 + g + half * 8;
            if (row >= MROWS) continue;
            int b = row / SS, s = row - b * SS;
#pragma unroll
            for (int jn = 0; jn < 8; jn++) {
                int n = col0 + wx * 64 + jn * 8 + m2;
                float v0 = acc[f][jn][half * 2 + 0];
                float v1 = acc[f][jn][half * 2 + 1];
                if (mode == 0) {
                    int c3 = n >> 8, rem = n & 255;
                    int h = rem >> 5, d = rem & 31;
                    int bh = b * NH + h;
                    if (c3 == 0) {
                        *(__half2*)&g_q[((size_t)bh * SP + s) * HD + d] =
                            __floats2half2_rn(v0 * QSCALE, v1 * QSCALE);
                    } else if (c3 == 1) {
                        *(__half2*)&g_k[((size_t)bh * SP + s) * HD + d] =
                            __floats2half2_rn(v0, v1);
                    } else {
                        g_vt[((size_t)bh * HD + d) * SP + s]     = __float2half(v0);
                        g_vt[((size_t)bh * HD + d + 1) * SP + s] = __float2half(v1);
                    }
                } else {
                    v0 += bias[n]; v1 += bias[n + 1];
                    if (s == 0)
                        *(float2*)&out_cls[(size_t)b * CC + n] = make_float2(v0, v1);
                    else
                        *(float2*)&out_x[((size_t)b * NN + (s - 1)) * CC + n] =
                            make_float2(v0, v1);
                }
            }
        }
    }
}

// ---------------------------------------------------------------------------
// V column sums, two-stage (wide):
//  a) 256 blocks: partial column sums of x (49 rows each)
//  b) 4 blocks: reduce partials + cls, multiply by Wv^T row -> g_vsum
// ---------------------------------------------------------------------------
__global__ __launch_bounds__(256) void vsum_a_kernel(const float* __restrict__ x)
{
    const int blk = blockIdx.x;          // b*64 + chunk
    const int b   = blk >> 6, ch = blk & 63;
    const int c   = threadIdx.x;
    const float* p = x + ((size_t)b * NN + ch * 49) * CC + c;
    float s = 0.f;
#pragma unroll 7
    for (int r = 0; r < 49; r++) s += p[(size_t)r * CC];
    g_xpart[blk][c] = s;
}

__global__ __launch_bounds__(256) void vsum_b_kernel(
    const float* __restrict__ cls, const float* __restrict__ qkv_w)
{
    __shared__ float xs[256];
    const int b = blockIdx.x;
    const int t = threadIdx.x;
    float s = cls[b * CC + t];
#pragma unroll
    for (int k = 0; k < 64; k++) s += g_xpart[b * 64 + k][t];
    xs[t] = s;
    __syncthreads();
    const float* wr = qkv_w + (size_t)(2 * CC + t) * CC;   // Wv row t
    float acc = 0.f;
#pragma unroll 8
    for (int cc = 0; cc < CC; cc++) acc += xs[cc] * wr[cc];
    g_vsum[b * CC + t] = acc;
}

// ---------------------------------------------------------------------------
// Flash attention, fp16 mma.sync, mean-subtracted PV (unchanged from R9)
// ---------------------------------------------------------------------------
#define TKEY 64
#define QTILE 128
#define STK 40
#define STV 72
#define KT_TILES (SP / TKEY)   // 50

__global__ __launch_bounds__(256, 2) void attn_mma_kernel()
{
    __shared__ alignas(16) uint16_t Kbuf[2][64 * STK];
    __shared__ alignas(16) uint16_t Vbuf[2][32 * STV];

    const int t    = threadIdx.x;
    const int w    = t >> 5;
    const int lane = t & 31;
    const int g    = lane >> 2;
    const int m2   = (lane & 3) * 2;
    const int bh   = blockIdx.y;
    const int q0   = blockIdx.x * QTILE;
    const int qrow = q0 + w * 16;

    const int kr = t >> 2, kc4 = t & 3;
    const int vr = t >> 3, vc8 = t & 7;
    const __half* gk = g_k + (size_t)bh * SP * HD;
    const __half* gv = g_vt + (size_t)bh * HD * SP + (size_t)vr * SP;
    uint32_t kdst[2], vdst[2];
    kdst[0] = smem_u32(&Kbuf[0][kr * STK + kc4 * 8]);
    kdst[1] = smem_u32(&Kbuf[1][kr * STK + kc4 * 8]);
    vdst[0] = smem_u32(&Vbuf[0][vr * STV + vc8 * 8]);
    vdst[1] = smem_u32(&Vbuf[1][vr * STV + vc8 * 8]);

    uint32_t kmat[2], vmat[2];
    {
        uint32_t ko = ((lane & 7) * STK + (lane >> 3) * 8) * 2;
        uint32_t vo = ((lane & 7) * STV + (lane >> 3) * 8) * 2;
        kmat[0] = smem_u32(Kbuf[0]) + ko; kmat[1] = smem_u32(Kbuf[1]) + ko;
        vmat[0] = smem_u32(Vbuf[0]) + vo; vmat[1] = smem_u32(Vbuf[1]) + vo;
    }

    uint32_t qa[2][4];
    {
        const __half* qb = g_q + (size_t)bh * SP * HD;
        int r0 = qrow + g, r1 = qrow + g + 8;
#pragma unroll
        for (int kc = 0; kc < 2; kc++) {
            int d0 = kc * 16 + m2, d1 = d0 + 8;
            qa[kc][0] = *(const uint32_t*)(qb + (size_t)r0 * HD + d0);
            qa[kc][1] = *(const uint32_t*)(qb + (size_t)r1 * HD + d0);
            qa[kc][2] = *(const uint32_t*)(qb + (size_t)r0 * HD + d1);
            qa[kc][3] = *(const uint32_t*)(qb + (size_t)r1 * HD + d1);
        }
    }

    float o[4][4];
#pragma unroll
    for (int i = 0; i < 4; i++)
#pragma unroll
        for (int j = 0; j < 4; j++) o[i][j] = 0.f;
    float la = 0.f, lb = 0.f;
    const uint32_t ONE2 = 0x3C003C00u;

    {
        CP16(kdst[0], gk + (size_t)kr * HD + kc4 * 8);
        CP16(vdst[0], gv + vc8 * 8);
        CPCOMMIT();
    }

    for (int kt = 0; kt < KT_TILES; kt++) {
        const int cur = kt & 1;
        __syncthreads();
        if (kt + 1 < KT_TILES) {
            int nk = kt + 1;
            CP16(kdst[cur ^ 1], gk + (size_t)(nk * TKEY + kr) * HD + kc4 * 8);
            CP16(vdst[cur ^ 1], gv + nk * TKEY + vc8 * 8);
        }
        CPCOMMIT();
        CPWAIT1();
        __syncthreads();

        float sf[8][4];
#pragma unroll
        for (int jn = 0; jn < 8; jn++) {
            uint32_t kb4[4];
            ldm4(kb4, kmat[cur] + jn * (8 * STK * 2));
            sf[jn][0] = sf[jn][1] = sf[jn][2] = sf[jn][3] = 0.f;
            mma16816h(sf[jn], qa[0], kb4 + 0, sf[jn]);
            mma16816h(sf[jn], qa[1], kb4 + 2, sf[jn]);
        }

        uint32_t fh[8][2];
        if (kt < KT_TILES - 1) {
            uint32_t t01[8], t23[8];
#pragma unroll
            for (int jn = 0; jn < 8; jn++) {
                uint32_t p01 = ex2h2(packh(sf[jn][0], sf[jn][1]));
                uint32_t p23 = ex2h2(packh(sf[jn][2], sf[jn][3]));
                fh[jn][0] = hsub2u(p01, ONE2);
                fh[jn][1] = hsub2u(p23, ONE2);
                t01[jn] = p01; t23[jn] = p23;
            }
            uint32_t a0 = hadd2u(hadd2u(t01[0], t01[1]), hadd2u(t01[2], t01[3]));
            uint32_t a1 = hadd2u(hadd2u(t01[4], t01[5]), hadd2u(t01[6], t01[7]));
            uint32_t b0 = hadd2u(hadd2u(t23[0], t23[1]), hadd2u(t23[2], t23[3]));
            uint32_t b1 = hadd2u(hadd2u(t23[4], t23[5]), hadd2u(t23[6], t23[7]));
            a0 = hadd2u(a0, a1);
            b0 = hadd2u(b0, b1);
            __half2 ha = *(__half2*)&a0;
            __half2 hb = *(__half2*)&b0;
            la += __low2float(ha) + __high2float(ha);
            lb += __low2float(hb) + __high2float(hb);
        } else {
            const int kb = kt * TKEY;
#pragma unroll
            for (int jn = 0; jn < 8; jn++) {
                int col0 = kb + jn * 8 + m2;
                bool c0v = col0 < SS, c1v = (col0 + 1) < SS;
                float p0 = c0v ? ex2(sf[jn][0]) : 0.f;
                float p1 = c1v ? ex2(sf[jn][1]) : 0.f;
                float p2 = c0v ? ex2(sf[jn][2]) : 0.f;
                float p3 = c1v ? ex2(sf[jn][3]) : 0.f;
                la += p0 + p1;
                lb += p2 + p3;
                fh[jn][0] = packh(c0v ? (p0 - 1.f) : 0.f, c1v ? (p1 - 1.f) : 0.f);
                fh[jn][1] = packh(c0v ? (p2 - 1.f) : 0.f, c1v ? (p3 - 1.f) : 0.f);
            }
        }

        uint32_t pa[4][4];
#pragma unroll
        for (int kc2 = 0; kc2 < 4; kc2++) {
            pa[kc2][0] = fh[2 * kc2][0];
            pa[kc2][1] = fh[2 * kc2][1];
            pa[kc2][2] = fh[2 * kc2 + 1][0];
            pa[kc2][3] = fh[2 * kc2 + 1][1];
        }
#pragma unroll
        for (int jn2 = 0; jn2 < 4; jn2++) {
            uint32_t vv[8];
            ldm4(vv,     vmat[cur] + jn2 * (8 * STV * 2));
            ldm4(vv + 4, vmat[cur] + jn2 * (8 * STV * 2) + 64);
#pragma unroll
            for (int kc2 = 0; kc2 < 4; kc2++)
                mma16816h(o[jn2], pa[kc2], vv + 2 * kc2, o[jn2]);
        }
    }

    la += __shfl_xor_sync(0xffffffffu, la, 1);
    la += __shfl_xor_sync(0xffffffffu, la, 2);
    lb += __shfl_xor_sync(0xffffffffu, lb, 1);
    lb += __shfl_xor_sync(0xffffffffu, lb, 2);
    const float ia = 1.f / la, ib = 1.f / lb;

    const int b = bh >> 3;
    const int h = bh & 7;
    const int r0 = qrow + g, r1 = qrow + g + 8;
#pragma unroll
    for (int jn2 = 0; jn2 < 4; jn2++) {
        float2 vs = *(const float2*)&g_vsum[b * CC + h * HD + jn2 * 8 + m2];
        if (r0 < SS) {
            float* dst = g_attn + ((size_t)b * SS + r0) * CC + h * HD + jn2 * 8 + m2;
            *(float2*)dst = make_float2((o[jn2][0] + vs.x) * ia,
                                        (o[jn2][1] + vs.y) * ia);
        }
        if (r1 < SS) {
            float* dst = g_attn + ((size_t)b * SS + r1) * CC + h * HD + jn2 * 8 + m2;
            *(float2*)dst = make_float2((o[jn2][2] + vs.x) * ib,
                                        (o[jn2][3] + vs.y) * ib);
        }
    }
}

// ---------------------------------------------------------------------------
// LePE: 5x5 depthwise conv (SAME), sliding-window version (unchanged)
// ---------------------------------------------------------------------------
#define XG 14
__global__ __launch_bounds__(256) void lepe_kernel(
    const float* __restrict__ x, const float* __restrict__ lw,
    const float* __restrict__ lb)
{
    __shared__ float wsh[25][256];
    const int c  = threadIdx.x;
    const int x0 = blockIdx.x * XG;
    const int y  = blockIdx.y;
    const int b  = blockIdx.z;

    for (int i = c; i < 25 * 256; i += 256)
        wsh[i % 25][i / 25] = lw[i];
    __syncthreads();
    float wt[25];
#pragma unroll
    for (int k = 0; k < 25; k++) wt[k] = wsh[k][c];
    const float lbv = lb[c];

    const float* xb = x + (size_t)b * HH * WW * CC + c;
    bool rv[5];
#pragma unroll
    for (int ky = 0; ky < 5; ky++) rv[ky] = (unsigned)(y + ky - 2) < (unsigned)HH;

    float win[5][5];
#pragma unroll
    for (int j = 0; j < 4; j++) {
        int col = x0 + j - 2;
        bool cv = (unsigned)col < (unsigned)WW;
#pragma unroll
        for (int ky = 0; ky < 5; ky++)
            win[j][ky] = (cv && rv[ky])
                ? xb[((size_t)(y + ky - 2) * WW + col) * CC] : 0.f;
    }

#pragma unroll
    for (int i = 0; i < XG; i++) {
        const int slot = (i + 4) % 5;
        int col = x0 + i + 2;
        bool cv = col < WW;
#pragma unroll
        for (int ky = 0; ky < 5; ky++)
            win[slot][ky] = (cv && rv[ky])
                ? xb[((size_t)(y + ky - 2) * WW + col) * CC] : 0.f;

        float sum = lbv;
#pragma unroll
        for (int kx = 0; kx < 5; kx++) {
            const int s = (i + kx) % 5;
#pragma unroll
            for (int ky = 0; ky < 5; ky++)
                sum += win[s][ky] * wt[ky * 5 + kx];
        }
        g_attn[((size_t)b * SS + 1 + y * WW + x0 + i) * CC + c] += sum;
    }
}

// ---------------------------------------------------------------------------
extern "C" void kernel_launch(void* const* d_in, const int* in_sizes, int n_in,
                              void* d_out, int out_size)
{
    const float* x      = (const float*)d_in[0];
    const float* cls    = (const float*)d_in[1];
    const float* qkv_w  = (const float*)d_in[2];
    const float* proj_w = (const float*)d_in[3];
    const float* proj_b = (const float*)d_in[4];
    const float* lepe_w = (const float*)d_in[5];
    const float* lepe_b = (const float*)d_in[6];

    float* out_x   = (float*)d_out;
    float* out_cls = (float*)d_out + in_sizes[0];

    // 0) exact fp32 V column sums (two-stage, wide)
    vsum_a_kernel<<<256, 256>>>(x);
    vsum_b_kernel<<<BB, 256>>>(cls, qkv_w);

    // 1) QKV projection on tensor cores -> fp16 Q (pre-scaled), K, V^T
    hgemm_kernel<<<dim3((MROWS + 127) / 128, 768 / 128), 256>>>(
        x, cls, qkv_w, nullptr, nullptr, nullptr, 0);

    // 2) fp16 mma.sync flash attention (mean-subtracted PV, f16x2 epilogue)
    attn_mma_kernel<<<dim3((SS + QTILE - 1) / QTILE, BHN), 256>>>();

    // 3) LePE depthwise conv added into g_attn (sliding window)
    lepe_kernel<<<dim3(WW / XG, HH, BB), 256>>>(x, lepe_w, lepe_b);

    // 4) Output projection on tensor cores
    hgemm_kernel<<<dim3((MROWS + 127) / 128, CC / 128), 256>>>(
        nullptr, nullptr, proj_w, proj_b, out_x, out_cls, 1);
}